// round 1
// baseline (speedup 1.0000x reference)
#include <cuda_runtime.h>

// HCEN forward: out = (mean_S(x) @ W_enc^T + b_enc) @ W_out^T + b_out
// Shapes: x[16,4096,1024] f32, W_enc[1024,1024], b_enc[1024], W_out[1024,1024], b_out[1024]
// HBM-bound: 256 MB read of x dominates (~32 us floor at ~8 TB/s).

#define BATCH 16
#define SEQ   4096
#define DIM   1024          // D_IN = H = D_OUT
#define NCHUNK 32
#define SCHUNK (SEQ / NCHUNK)   // 128

// Device-global scratch (no allocation allowed in kernel_launch).
__device__ float g_partials[NCHUNK * BATCH * DIM];  // 2 MB
__device__ float g_m[BATCH * DIM];                  // 64 KB
__device__ float g_enc[BATCH * DIM];                // 64 KB

// ---------------------------------------------------------------------------
// Pass 1: partial sums over S-chunks. grid (16, 32), block 256.
// Each thread owns one float4 column group (4 of the 1024 dims) and sums 128
// rows. Loads are fully coalesced: 256 threads x 16B = one 4 KB row per step.
// ---------------------------------------------------------------------------
__global__ void mean_partial_kernel(const float* __restrict__ x) {
    const int b = blockIdx.x;
    const int c = blockIdx.y;
    const int t = threadIdx.x;  // 0..255

    const float4* __restrict__ x4 =
        reinterpret_cast<const float4*>(x + ((size_t)b * SEQ + (size_t)c * SCHUNK) * DIM);

    float4 acc = make_float4(0.f, 0.f, 0.f, 0.f);
#pragma unroll 8
    for (int s = 0; s < SCHUNK; s++) {
        float4 v = x4[(size_t)s * (DIM / 4) + t];
        acc.x += v.x; acc.y += v.y; acc.z += v.z; acc.w += v.w;
    }
    reinterpret_cast<float4*>(g_partials)[((size_t)c * BATCH + b) * (DIM / 4) + t] = acc;
}

// ---------------------------------------------------------------------------
// Pass 2: reduce 32 chunk partials -> mean. grid 16, block 256.
// ---------------------------------------------------------------------------
__global__ void mean_reduce_kernel() {
    const int b = blockIdx.x;
    const int t = threadIdx.x;

    float4 acc = make_float4(0.f, 0.f, 0.f, 0.f);
#pragma unroll
    for (int c = 0; c < NCHUNK; c++) {
        float4 v = reinterpret_cast<const float4*>(g_partials)[((size_t)c * BATCH + b) * (DIM / 4) + t];
        acc.x += v.x; acc.y += v.y; acc.z += v.z; acc.w += v.w;
    }
    const float inv = 1.0f / (float)SEQ;
    acc.x *= inv; acc.y *= inv; acc.z *= inv; acc.w *= inv;
    reinterpret_cast<float4*>(g_m)[(size_t)b * (DIM / 4) + t] = acc;
}

// ---------------------------------------------------------------------------
// Pass 3/4: tiny GEMM  out[b][h] = dot(A[b], W[h]) + bias[h]
// A is [16,1024]. Block = 256 threads = 8 warps; one warp per h; 8 batches
// per block staged in 32 KB static shared. grid (DIM/8, 2).
// stage 0: A = g_m,   out = g_enc
// stage 1: A = g_enc, out = dout (harness output)
// (globals selected in device code so kernel_launch is pure kernel launches)
// ---------------------------------------------------------------------------
__global__ void gemm8_kernel(int stage,
                             const float* __restrict__ W,
                             const float* __restrict__ bias,
                             float* __restrict__ dout) {
    __shared__ float sm[8 * DIM];  // 32 KB

    const float* __restrict__ A = (stage == 0) ? g_m : g_enc;
    float* __restrict__ out     = (stage == 0) ? g_enc : dout;

    const int t    = threadIdx.x;
    const int w    = t >> 5;
    const int lane = t & 31;
    const int b0   = blockIdx.y * 8;

    // Stage 8 rows of A into shared (8 KB of float4s, 8 per thread).
    const float4* __restrict__ A4 = reinterpret_cast<const float4*>(A);
    float4* sm4 = reinterpret_cast<float4*>(sm);
#pragma unroll
    for (int i = 0; i < 8; i++) {
        int idx = t + i * 256;  // 0..2047
        sm4[idx] = A4[(size_t)b0 * (DIM / 4) + idx];
    }
    __syncthreads();

    const int h = blockIdx.x * 8 + w;
    const float4* __restrict__ W4 = reinterpret_cast<const float4*>(W + (size_t)h * DIM);

    float acc[8];
#pragma unroll
    for (int b = 0; b < 8; b++) acc[b] = 0.f;

#pragma unroll
    for (int it = 0; it < 8; it++) {
        const int j = it * 32 + lane;     // float4 index within row, 0..255
        const float4 wv = W4[j];
#pragma unroll
        for (int b = 0; b < 8; b++) {
            const float4 mv = sm4[b * (DIM / 4) + j];
            acc[b] += wv.x * mv.x + wv.y * mv.y + wv.z * mv.z + wv.w * mv.w;
        }
    }

    const float bv = bias[h];
#pragma unroll
    for (int b = 0; b < 8; b++) {
        float v = acc[b];
#pragma unroll
        for (int off = 16; off > 0; off >>= 1)
            v += __shfl_down_sync(0xffffffffu, v, off);
        if (lane == 0)
            out[(size_t)(b0 + b) * DIM + h] = v + bv;
    }
}

extern "C" void kernel_launch(void* const* d_in, const int* in_sizes, int n_in,
                              void* d_out, int out_size) {
    const float* x     = (const float*)d_in[0];
    const float* W_enc = (const float*)d_in[1];
    const float* b_enc = (const float*)d_in[2];
    const float* W_out = (const float*)d_in[3];
    const float* b_out = (const float*)d_in[4];
    float* out = (float*)d_out;

    (void)in_sizes; (void)n_in; (void)out_size;

    mean_partial_kernel<<<dim3(BATCH, NCHUNK), 256>>>(x);
    mean_reduce_kernel<<<BATCH, 256>>>();
    gemm8_kernel<<<dim3(DIM / 8, 2), 256>>>(0, W_enc, b_enc, nullptr);
    gemm8_kernel<<<dim3(DIM / 8, 2), 256>>>(1, W_out, b_out, out);
}